// round 1
// baseline (speedup 1.0000x reference)
#include <cuda_runtime.h>

// Fused per-graph GNN kernel.
// Input order (metadata.txt == setup_inputs dict order):
//  0 x_my [N,32]      1 x_opp [N,32]    2 W_enc [32,128]   3 b_enc [128]
//  4 gb_Wl [2,128,512] 5 gb_Wr          6 gb_att [2,4,128] 7 gb_b [2,128]
//  8 gr_Wl             9 gr_Wr         10 gr_att          11 gr_b
// 12 cl_Wf [2,256,128] 13 cl_bf [2,128] 14 cl_Ws 15 cl_bs
// 16 cr_Wf 17 cr_bf 18 cr_Ws 19 cr_bs
// 20 node_W [2,128,128] 21 node_b [2,128]
// 22 W1 [256,128] 23 b1 [128] 24 W2 [128,1] 25 b2 [1]
// 26..29 edge indices (ignored: full bipartite per graph), 30..31 batch (ignored)

namespace {
constexpr int NPH  = 10;
constexpr int Hd   = 128;
constexpr int NHEADS = 4;
constexpr int CDm  = 32;
constexpr int TPB  = 256;

// shared layout (floats)
constexpr int OFF_XM  = 0;          // [10][128]
constexpr int OFF_XO  = 1280;
constexpr int OFF_NM  = 2560;
constexpr int OFF_NO  = 3840;
constexpr int OFF_A   = 5120;       // 5120 floats: XL / {Fd,Fs,Sd,Ss} / staging
constexpr int OFF_B   = 10240;      // 5120 floats: XR
constexpr int OFF_LOG = 15360;      // 400
constexpr int OFF_POOL= 15760;      // 256
constexpr int OFF_H   = 16016;      // 256
constexpr int SMEM_FLOATS = 16272;
constexpr int SMEM_BYTES  = SMEM_FLOATS * 4;
}

// GATv2 relation: s_src -> s_dst aggregation, writes/accumulates into s_out.
__device__ __forceinline__ void gatv2_block(
    const float* __restrict__ s_src, const float* __restrict__ s_dst,
    const float* __restrict__ Wl, const float* __restrict__ Wr,
    const float* __restrict__ att, const float* __restrict__ bias,
    float* s_XL, float* s_XR, float* s_log, float* s_out, bool accum)
{
    const int t = threadIdx.x;

    // ---- GEMMs: XL = src @ Wl, XR = dst @ Wr   ([10,128] @ [128,512]) ----
    {
        float aL0[NPH], aL1[NPH], aR0[NPH], aR1[NPH];
#pragma unroll
        for (int r = 0; r < NPH; r++) { aL0[r]=0.f; aL1[r]=0.f; aR0[r]=0.f; aR1[r]=0.f; }
        const int c0 = t, c1 = t + 256;
#pragma unroll 4
        for (int k = 0; k < Hd; k++) {
            const float wl0 = Wl[k*512 + c0];
            const float wl1 = Wl[k*512 + c1];
            const float wr0 = Wr[k*512 + c0];
            const float wr1 = Wr[k*512 + c1];
#pragma unroll
            for (int r = 0; r < NPH; r++) {
                const float xs = s_src[r*Hd + k];
                const float xd = s_dst[r*Hd + k];
                aL0[r] = fmaf(xs, wl0, aL0[r]);
                aL1[r] = fmaf(xs, wl1, aL1[r]);
                aR0[r] = fmaf(xd, wr0, aR0[r]);
                aR1[r] = fmaf(xd, wr1, aR1[r]);
            }
        }
#pragma unroll
        for (int r = 0; r < NPH; r++) {
            s_XL[r*512 + c0] = aL0[r]; s_XL[r*512 + c1] = aL1[r];
            s_XR[r*512 + c0] = aR0[r]; s_XR[r*512 + c1] = aR1[r];
        }
    }
    __syncthreads();

    // ---- logits[h,j,i] = sum_c leaky(XL[i,h,c]+XR[j,h,c]) * att[h,c] (warp per logit) ----
    {
        const int warp = t >> 5, lane = t & 31;
        for (int id = warp; id < NHEADS*NPH*NPH; id += TPB/32) {
            const int h = id / 100;
            const int j = (id % 100) / 10;
            const int i = id % 10;
            const float* xl = s_XL + i*512 + h*Hd;
            const float* xr = s_XR + j*512 + h*Hd;
            const float* at = att + h*Hd;
            float p = 0.f;
#pragma unroll
            for (int cc = 0; cc < 4; cc++) {
                const int c = lane + cc*32;
                float e = xl[c] + xr[c];
                e = (e >= 0.f) ? e : 0.2f * e;
                p = fmaf(e, at[c], p);
            }
#pragma unroll
            for (int o = 16; o > 0; o >>= 1) p += __shfl_xor_sync(0xffffffffu, p, o);
            if (lane == 0) s_log[id] = p;   // [h*100 + j*10 + i]
        }
    }
    __syncthreads();

    // ---- softmax over i per (h, j) ----
    if (t < NHEADS*NPH) {
        float* lg = s_log + t*10;
        float m = lg[0];
#pragma unroll
        for (int i = 1; i < 10; i++) m = fmaxf(m, lg[i]);
        float a[10]; float sum = 0.f;
#pragma unroll
        for (int i = 0; i < 10; i++) { a[i] = __expf(lg[i] - m); sum += a[i]; }
        const float inv = __fdividef(1.f, sum);
#pragma unroll
        for (int i = 0; i < 10; i++) lg[i] = a[i] * inv;
    }
    __syncthreads();

    // ---- out[j,c] = bias[c] + 0.25 * sum_h sum_i alpha[h,j,i] * XL[i,h,c] ----
    {
        const int c  = t & 127;
        const int rh = t >> 7;
#pragma unroll
        for (int jj = 0; jj < 5; jj++) {
            const int j = rh*5 + jj;
            float acc = 0.f;
#pragma unroll
            for (int h = 0; h < NHEADS; h++) {
                const float* al = s_log + h*100 + j*10;
                const float* xl = s_XL + h*Hd + c;
#pragma unroll
                for (int i = 0; i < 10; i++) acc = fmaf(al[i], xl[i*512], acc);
            }
            const float v = acc * 0.25f + bias[c];
            if (accum) s_out[j*Hd + c] += v; else s_out[j*Hd + c] = v;
        }
    }
    __syncthreads();
}

// CGConv relation: out_i = x_dst_i + sum_j sigmoid(Fd_i+Fs_j) * softplus(Sd_i+Ss_j)
// where F/S halves are per-node GEMMs (factorized concat).
__device__ __forceinline__ void cgconv_block(
    const float* __restrict__ s_src, const float* __restrict__ s_dst,
    const float* __restrict__ Wf, const float* __restrict__ bf,
    const float* __restrict__ Ws, const float* __restrict__ bs,
    float* s_F, float* s_out, bool accum)
{
    const int t   = threadIdx.x;
    const int c   = t & 127;
    const int sel = t >> 7;                  // 0 -> f-branch, 1 -> s-branch
    const float* W  = sel ? Ws : Wf;
    const float* bb = sel ? bs : bf;

    float aD[NPH], aS[NPH];
#pragma unroll
    for (int r = 0; r < NPH; r++) { aD[r] = 0.f; aS[r] = 0.f; }
#pragma unroll 4
    for (int k = 0; k < Hd; k++) {
        const float wD = W[k*Hd + c];        // rows 0..127 multiply x_dst
        const float wS = W[(k+Hd)*Hd + c];   // rows 128..255 multiply x_src
#pragma unroll
        for (int r = 0; r < NPH; r++) {
            aD[r] = fmaf(s_dst[r*Hd + k], wD, aD[r]);
            aS[r] = fmaf(s_src[r*Hd + k], wS, aS[r]);
        }
    }
    const float bv = bb[c];
    float* FD = s_F + sel*2560;   // f: [0,1280)+[1280,2560)  s: [2560,3840)+[3840,5120)
    float* FS = FD + 1280;
#pragma unroll
    for (int r = 0; r < NPH; r++) {
        FD[r*Hd + c] = aD[r] + bv;           // bias folded into dst half
        FS[r*Hd + c] = aS[r];
    }
    __syncthreads();

    {
        const int rh = t >> 7;
        const float* Fd = s_F;
        const float* Fs = s_F + 1280;
        const float* Sd = s_F + 2560;
        const float* Ss = s_F + 3840;
#pragma unroll
        for (int jj = 0; jj < 5; jj++) {
            const int i = rh*5 + jj;
            const float fd = Fd[i*Hd + c];
            const float sd = Sd[i*Hd + c];
            float acc = s_dst[i*Hd + c];     // residual
#pragma unroll
            for (int j = 0; j < 10; j++) {
                const float f = fd + Fs[j*Hd + c];
                const float s = sd + Ss[j*Hd + c];
                const float sig = __fdividef(1.f, 1.f + __expf(-f));
                const float sp  = fmaxf(s, 0.f) + __logf(1.f + __expf(-fabsf(s)));
                acc = fmaf(sig, sp, acc);
            }
            if (accum) s_out[i*Hd + c] += acc; else s_out[i*Hd + c] = acc;
        }
    }
    __syncthreads();
}

// two [10,128]@[128,128]+b in parallel (sel picks which)
__device__ __forceinline__ void dual_linear_block(
    const float* __restrict__ s_in0, const float* __restrict__ s_in1,
    const float* __restrict__ W, const float* __restrict__ b,
    float* s_out0, float* s_out1)
{
    const int t = threadIdx.x;
    const int c = t & 127;
    const int sel = t >> 7;
    const float* sin = sel ? s_in1 : s_in0;
    float* sout      = sel ? s_out1 : s_out0;
    float acc[NPH];
#pragma unroll
    for (int r = 0; r < NPH; r++) acc[r] = 0.f;
#pragma unroll 4
    for (int k = 0; k < Hd; k++) {
        const float w = W[k*Hd + c];
#pragma unroll
        for (int r = 0; r < NPH; r++) acc[r] = fmaf(sin[r*Hd + k], w, acc[r]);
    }
    const float bv = b[c];
#pragma unroll
    for (int r = 0; r < NPH; r++) sout[r*Hd + c] = acc[r] + bv;
    __syncthreads();
}

extern "C" __global__ void __launch_bounds__(TPB)
yomi_kernel(
    const float* __restrict__ x_my,  const float* __restrict__ x_opp,
    const float* __restrict__ W_enc, const float* __restrict__ b_enc,
    const float* __restrict__ gb_Wl, const float* __restrict__ gb_Wr,
    const float* __restrict__ gb_att,const float* __restrict__ gb_b,
    const float* __restrict__ gr_Wl, const float* __restrict__ gr_Wr,
    const float* __restrict__ gr_att,const float* __restrict__ gr_b,
    const float* __restrict__ cl_Wf, const float* __restrict__ cl_bf,
    const float* __restrict__ cl_Ws, const float* __restrict__ cl_bs,
    const float* __restrict__ cr_Wf, const float* __restrict__ cr_bf,
    const float* __restrict__ cr_Ws, const float* __restrict__ cr_bs,
    const float* __restrict__ node_W,const float* __restrict__ node_b,
    const float* __restrict__ W1,    const float* __restrict__ b1,
    const float* __restrict__ W2,    const float* __restrict__ b2,
    float* __restrict__ out)
{
    extern __shared__ float sm[];
    float* s_xm  = sm + OFF_XM;
    float* s_xo  = sm + OFF_XO;
    float* s_nm  = sm + OFF_NM;
    float* s_no  = sm + OFF_NO;
    float* s_A   = sm + OFF_A;
    float* s_B   = sm + OFF_B;
    float* s_log = sm + OFF_LOG;
    float* s_pool= sm + OFF_POOL;
    float* s_h   = sm + OFF_H;

    const int g = blockIdx.x;
    const int t = threadIdx.x;

    // ---- encoder: stage x rows, then [10,32]@[32,128]+b ----
    {
        for (int idx = t; idx < NPH*CDm; idx += TPB) {
            s_A[idx]       = x_my [g*NPH*CDm + idx];
            s_A[512 + idx] = x_opp[g*NPH*CDm + idx];
        }
        __syncthreads();
        const int c = t & 127;
        const int sel = t >> 7;
        const float* xg = s_A + sel*512;
        float acc[NPH];
#pragma unroll
        for (int r = 0; r < NPH; r++) acc[r] = 0.f;
#pragma unroll
        for (int k = 0; k < CDm; k++) {
            const float w = W_enc[k*Hd + c];
#pragma unroll
            for (int r = 0; r < NPH; r++) acc[r] = fmaf(xg[r*CDm + k], w, acc[r]);
        }
        const float bv = b_enc[c];
        float* dst = sel ? s_xo : s_xm;
#pragma unroll
        for (int r = 0; r < NPH; r++) dst[r*Hd + c] = acc[r] + bv;
        __syncthreads();
    }

    // ---- 2 hetero layers ----
#pragma unroll 1
    for (int l = 0; l < 2; l++) {
        const int wG = l * Hd * 512;     // GAT weight stride
        const int wC = l * 2*Hd * Hd;    // CGConv weight stride
        const int wN = l * Hd * Hd;      // node linear stride
        const int wb = l * Hd;
        // new_xo = gat_beats(xm->xo) + cg_loses(xm->xo)
        gatv2_block(s_xm, s_xo, gb_Wl + wG, gb_Wr + wG, gb_att + l*NHEADS*Hd,
                    gb_b + wb, s_A, s_B, s_log, s_no, false);
        cgconv_block(s_xm, s_xo, cl_Wf + wC, cl_bf + wb, cl_Ws + wC, cl_bs + wb,
                     s_A, s_no, true);
        // new_xm = cg_rev(xo->xm) + gat_rev(xo->xm)
        cgconv_block(s_xo, s_xm, cr_Wf + wC, cr_bf + wb, cr_Ws + wC, cr_bs + wb,
                     s_A, s_nm, false);
        gatv2_block(s_xo, s_xm, gr_Wl + wG, gr_Wr + wG, gr_att + l*NHEADS*Hd,
                    gr_b + wb, s_A, s_B, s_log, s_nm, true);
        // node linear
        dual_linear_block(s_nm, s_no, node_W + wN, node_b + wb, s_xm, s_xo);
    }

    // ---- mean pool per type, MLP head ----
    {
        const int c = t & 127;
        const int sel = t >> 7;
        const float* xp = sel ? s_xo : s_xm;
        float p = 0.f;
#pragma unroll
        for (int r = 0; r < NPH; r++) p += xp[r*Hd + c];
        s_pool[sel*Hd + c] = p * 0.1f;
    }
    __syncthreads();
    {
        const int c = t & 127;
        const int half = t >> 7;
        float a = 0.f;
#pragma unroll 4
        for (int kk = 0; kk < Hd; kk++) {
            const int k = half*Hd + kk;
            a = fmaf(s_pool[k], W1[k*Hd + c], a);
        }
        s_h[t] = a;
    }
    __syncthreads();
    if (t < Hd) {
        float hv = s_h[t] + s_h[Hd + t] + b1[t];
        hv = (hv >= 0.f) ? hv : 128.f * hv;   // LeakyReLU slope = final_dim = 128
        s_h[t] = hv * W2[t];
    }
    __syncthreads();
    if (t < 32) {
        float v = s_h[t] + s_h[t+32] + s_h[t+64] + s_h[t+96];
#pragma unroll
        for (int o = 16; o > 0; o >>= 1) v += __shfl_xor_sync(0xffffffffu, v, o);
        if (t == 0) out[g] = v + b2[0];
    }
}

extern "C" void kernel_launch(void* const* d_in, const int* in_sizes, int n_in,
                              void* d_out, int out_size)
{
    const float* x_my   = (const float*)d_in[0];
    const float* x_opp  = (const float*)d_in[1];
    const float* W_enc  = (const float*)d_in[2];
    const float* b_enc  = (const float*)d_in[3];
    const float* gb_Wl  = (const float*)d_in[4];
    const float* gb_Wr  = (const float*)d_in[5];
    const float* gb_att = (const float*)d_in[6];
    const float* gb_b   = (const float*)d_in[7];
    const float* gr_Wl  = (const float*)d_in[8];
    const float* gr_Wr  = (const float*)d_in[9];
    const float* gr_att = (const float*)d_in[10];
    const float* gr_b   = (const float*)d_in[11];
    const float* cl_Wf  = (const float*)d_in[12];
    const float* cl_bf  = (const float*)d_in[13];
    const float* cl_Ws  = (const float*)d_in[14];
    const float* cl_bs  = (const float*)d_in[15];
    const float* cr_Wf  = (const float*)d_in[16];
    const float* cr_bf  = (const float*)d_in[17];
    const float* cr_Ws  = (const float*)d_in[18];
    const float* cr_bs  = (const float*)d_in[19];
    const float* node_W = (const float*)d_in[20];
    const float* node_b = (const float*)d_in[21];
    const float* W1     = (const float*)d_in[22];
    const float* b1     = (const float*)d_in[23];
    const float* W2     = (const float*)d_in[24];
    const float* b2     = (const float*)d_in[25];

    const int n_nodes = in_sizes[0] / CDm;   // N = B * NPH
    const int nblocks = n_nodes / NPH;       // = B = 2048

    cudaFuncSetAttribute(yomi_kernel,
                         cudaFuncAttributeMaxDynamicSharedMemorySize, SMEM_BYTES);

    yomi_kernel<<<nblocks, TPB, SMEM_BYTES>>>(
        x_my, x_opp, W_enc, b_enc,
        gb_Wl, gb_Wr, gb_att, gb_b,
        gr_Wl, gr_Wr, gr_att, gr_b,
        cl_Wf, cl_bf, cl_Ws, cl_bs,
        cr_Wf, cr_bf, cr_Ws, cr_bs,
        node_W, node_b, W1, b1, W2, b2,
        (float*)d_out);
}

// round 2
// speedup vs baseline: 1.3044x; 1.3044x over previous
#include <cuda_runtime.h>

// Fused per-graph GNN kernel, FFMA2 (f32x2) edition.
// Activations live in a DUPLICATED smem layout: dup[r*256+2k] = dup[r*256+2k+1] = x[r][k]
// so fma.rn.f32x2 gets its broadcast operand for free from LDS.128.

typedef unsigned long long u64;

__device__ __forceinline__ void ffma2(u64& d, u64 a, u64 b) {
    asm("fma.rn.f32x2 %0, %1, %2, %0;" : "+l"(d) : "l"(a), "l"(b));
}
__device__ __forceinline__ u64 fadd2(u64 a, u64 b) {
    u64 d; asm("add.rn.f32x2 %0, %1, %2;" : "=l"(d) : "l"(a), "l"(b)); return d;
}
__device__ __forceinline__ float2 unpack2(u64 v) {
    float2 f; asm("mov.b64 {%0, %1}, %2;" : "=f"(f.x), "=f"(f.y) : "l"(v)); return f;
}

namespace {
constexpr int NPH = 10;
constexpr int Hd  = 128;
constexpr int CDm = 32;
constexpr int TPB = 256;

// smem offsets (floats)
constexpr int OFF_XM   = 0;       // dup [10][256]
constexpr int OFF_XO   = 2560;
constexpr int OFF_NM   = 5120;
constexpr int OFF_NO   = 7680;
constexpr int OFF_A    = 10240;   // 5120: XL / CG F-buffers / staging
constexpr int OFF_B    = 15360;   // 5120: XR
constexpr int OFF_LOG  = 20480;   // 40 * 20 = 800 (stride-20 logit rows)
constexpr int OFF_POOL = 21280;   // 256
constexpr int OFF_H    = 21536;   // 256
constexpr int SMEM_FLOATS = 21792;
constexpr int SMEM_BYTES  = SMEM_FLOATS * 4;
}

// ---------------- GATv2 relation ----------------
__device__ __forceinline__ void gatv2_block(
    const float* __restrict__ s_src_dup, const float* __restrict__ s_dst_dup,
    const float* __restrict__ Wl, const float* __restrict__ Wr,
    const float* __restrict__ att, const float* __restrict__ bias,
    float* s_XL, float* s_XR, float* s_log, float* s_out_dup, bool accum)
{
    const int t = threadIdx.x;

    // ---- GEMMs: XL = src @ Wl (t<128), XR = dst @ Wr (t>=128). 4 cols/thread ----
    {
        const bool isL = (t < 128);
        const int c4 = (t & 127) * 4;
        const float* __restrict__ W  = isL ? Wl : Wr;
        const float* __restrict__ xd = isL ? s_src_dup : s_dst_dup;
        u64 acc[NPH][2];
#pragma unroll
        for (int r = 0; r < NPH; r++) { acc[r][0] = 0ull; acc[r][1] = 0ull; }
#pragma unroll 2
        for (int k = 0; k < Hd; k += 4) {
            const ulonglong2 w0 = *(const ulonglong2*)&W[(k+0)*512 + c4];
            const ulonglong2 w1 = *(const ulonglong2*)&W[(k+1)*512 + c4];
            const ulonglong2 w2 = *(const ulonglong2*)&W[(k+2)*512 + c4];
            const ulonglong2 w3 = *(const ulonglong2*)&W[(k+3)*512 + c4];
#pragma unroll
            for (int r = 0; r < NPH; r++) {
                const ulonglong2 xa = *(const ulonglong2*)&xd[r*256 + 2*k];
                const ulonglong2 xb = *(const ulonglong2*)&xd[r*256 + 2*k + 4];
                ffma2(acc[r][0], xa.x, w0.x); ffma2(acc[r][1], xa.x, w0.y);
                ffma2(acc[r][0], xa.y, w1.x); ffma2(acc[r][1], xa.y, w1.y);
                ffma2(acc[r][0], xb.x, w2.x); ffma2(acc[r][1], xb.x, w2.y);
                ffma2(acc[r][0], xb.y, w3.x); ffma2(acc[r][1], xb.y, w3.y);
            }
        }
        float* outp = isL ? s_XL : s_XR;
#pragma unroll
        for (int r = 0; r < NPH; r++) {
            const float2 a = unpack2(acc[r][0]);
            const float2 b = unpack2(acc[r][1]);
            *(float4*)&outp[r*512 + c4] = make_float4(a.x, a.y, b.x, b.y);
        }
    }
    __syncthreads();

    // ---- logits: warp per (h,j) pair, 10 i's; leaky(e)=0.6e+0.4|e| ----
    {
        const int warp = t >> 5, lane = t & 31;
#pragma unroll
        for (int pp = 0; pp < 5; pp++) {
            const int p = warp + pp*8;            // 0..39 = h*10+j
            const int h = p / 10, j = p % 10;
            const float4 xr = *(const float4*)&s_XR[j*512 + h*Hd + lane*4];
            const float4 at = *(const float4*)&att[h*Hd + lane*4];
#pragma unroll
            for (int i = 0; i < NPH; i++) {
                const float4 xl = *(const float4*)&s_XL[i*512 + h*Hd + lane*4];
                float e, s;
                e = xl.x + xr.x; s = at.x * fmaf(e, 0.6f, 0.4f*fabsf(e));
                e = xl.y + xr.y; s = fmaf(at.y, fmaf(e, 0.6f, 0.4f*fabsf(e)), s);
                e = xl.z + xr.z; s = fmaf(at.z, fmaf(e, 0.6f, 0.4f*fabsf(e)), s);
                e = xl.w + xr.w; s = fmaf(at.w, fmaf(e, 0.6f, 0.4f*fabsf(e)), s);
#pragma unroll
                for (int o = 16; o > 0; o >>= 1) s += __shfl_xor_sync(0xffffffffu, s, o);
                if (lane == 0) s_log[p*20 + i] = s;
            }
        }
    }
    __syncthreads();

    // ---- softmax over i per (h,j) ----
    if (t < 40) {
        float* lg = s_log + t*20;
        float m = lg[0];
#pragma unroll
        for (int i = 1; i < NPH; i++) m = fmaxf(m, lg[i]);
        float a[NPH]; float sum = 0.f;
#pragma unroll
        for (int i = 0; i < NPH; i++) { a[i] = __expf(lg[i] - m); sum += a[i]; }
        const float inv = __fdividef(1.f, sum);
#pragma unroll
        for (int i = 0; i < NPH; i++) lg[i] = a[i] * inv;
    }
    __syncthreads();

    // ---- out[j,c] = bias + 0.25 * sum_h sum_i alpha[h,j,i]*XL[i,h,c] ----
    {
        const int c = t & 127, rh = t >> 7;
        float accj[5] = {0.f, 0.f, 0.f, 0.f, 0.f};
#pragma unroll
        for (int h = 0; h < 4; h++) {
            float xlh[NPH];
#pragma unroll
            for (int i = 0; i < NPH; i++) xlh[i] = s_XL[i*512 + h*Hd + c];
#pragma unroll
            for (int jj = 0; jj < 5; jj++) {
                const float* al = s_log + (h*10 + rh*5 + jj)*20;
                const float4 a0 = *(const float4*)al;
                const float4 a1 = *(const float4*)(al + 4);
                const float2 a2 = *(const float2*)(al + 8);
                float v = accj[jj];
                v = fmaf(a0.x, xlh[0], v); v = fmaf(a0.y, xlh[1], v);
                v = fmaf(a0.z, xlh[2], v); v = fmaf(a0.w, xlh[3], v);
                v = fmaf(a1.x, xlh[4], v); v = fmaf(a1.y, xlh[5], v);
                v = fmaf(a1.z, xlh[6], v); v = fmaf(a1.w, xlh[7], v);
                v = fmaf(a2.x, xlh[8], v); v = fmaf(a2.y, xlh[9], v);
                accj[jj] = v;
            }
        }
        const float bv = bias[c];
#pragma unroll
        for (int jj = 0; jj < 5; jj++) {
            const int j = rh*5 + jj;
            float v = accj[jj] * 0.25f + bv;
            if (accum) v += s_out_dup[j*256 + 2*c];
            *(float2*)&s_out_dup[j*256 + 2*c] = make_float2(v, v);
        }
    }
    __syncthreads();
}

// ---------------- CGConv relation ----------------
__device__ __forceinline__ void cgconv_block(
    const float* __restrict__ s_src_dup, const float* __restrict__ s_dst_dup,
    const float* __restrict__ Wf, const float* __restrict__ bf,
    const float* __restrict__ Ws, const float* __restrict__ bs,
    float* s_F, float* s_out_dup, bool accum)
{
    const int t = threadIdx.x;
    // thread = {f,s} x {D,S} x 64 col-pairs
    {
        const int fs   = t >> 7;
        const int half = (t >> 6) & 1;           // 0: dst rows, 1: src rows
        const int c0   = (t & 63) * 2;
        const float* __restrict__ W  = (fs ? Ws : Wf) + half*Hd*Hd;
        const float* __restrict__ xd = half ? s_src_dup : s_dst_dup;
        u64 acc[NPH];
#pragma unroll
        for (int r = 0; r < NPH; r++) acc[r] = 0ull;
#pragma unroll 2
        for (int k = 0; k < Hd; k += 4) {
            const u64 w0 = *(const u64*)&W[(k+0)*Hd + c0];
            const u64 w1 = *(const u64*)&W[(k+1)*Hd + c0];
            const u64 w2 = *(const u64*)&W[(k+2)*Hd + c0];
            const u64 w3 = *(const u64*)&W[(k+3)*Hd + c0];
#pragma unroll
            for (int r = 0; r < NPH; r++) {
                const ulonglong2 xa = *(const ulonglong2*)&xd[r*256 + 2*k];
                const ulonglong2 xb = *(const ulonglong2*)&xd[r*256 + 2*k + 4];
                ffma2(acc[r], xa.x, w0);
                ffma2(acc[r], xa.y, w1);
                ffma2(acc[r], xb.x, w2);
                ffma2(acc[r], xb.y, w3);
            }
        }
        float* F = s_F + fs*2560 + half*1280;    // [Fd|Fs|Sd|Ss], each [10][128]
        if (half == 0) {
            const float* bb = fs ? bs : bf;
            const u64 bv = *(const u64*)&bb[c0];
#pragma unroll
            for (int r = 0; r < NPH; r++) acc[r] = fadd2(acc[r], bv);
        }
#pragma unroll
        for (int r = 0; r < NPH; r++) {
            const float2 v = unpack2(acc[r]);
            *(float2*)&F[r*Hd + c0] = v;
        }
    }
    __syncthreads();

    // ---- elementwise: out_i = x_i + sum_j sigmoid(Fd_i+Fs_j)*softplus(Sd_i+Ss_j) ----
    {
        const int c = t & 127, rh = t >> 7;
        const float* Fd = s_F;
        const float* Fs = s_F + 1280;
        const float* Sd = s_F + 2560;
        const float* Ss = s_F + 3840;
#pragma unroll
        for (int jj = 0; jj < 5; jj++) {
            const int i = rh*5 + jj;
            const float fd = Fd[i*Hd + c];
            const float sd = Sd[i*Hd + c];
            float acc = s_dst_dup[i*256 + 2*c];   // residual
#pragma unroll
            for (int j = 0; j < NPH; j++) {
                const float f = fd + Fs[j*Hd + c];
                const float s = sd + Ss[j*Hd + c];
                const float sig = __fdividef(1.f, 1.f + __expf(-f));
                const float sp  = fmaxf(s, 0.f) + __logf(1.f + __expf(-fabsf(s)));
                acc = fmaf(sig, sp, acc);
            }
            if (accum) acc += s_out_dup[i*256 + 2*c];
            *(float2*)&s_out_dup[i*256 + 2*c] = make_float2(acc, acc);
        }
    }
    __syncthreads();
}

// ---------------- node linear (both matrices, split-k) ----------------
__device__ __forceinline__ void dual_linear_block(
    const float* __restrict__ s_in0_dup, const float* __restrict__ s_in1_dup,
    const float* __restrict__ W, const float* __restrict__ b,
    float* s_out0_dup, float* s_out1_dup, float* s_stage)
{
    const int t = threadIdx.x;
    const int sel = t >> 7;
    const int kh  = (t >> 6) & 1;
    const int pr  = t & 63;
    const int c0  = pr * 2;
    const float* __restrict__ in = sel ? s_in1_dup : s_in0_dup;
    u64 acc[NPH];
#pragma unroll
    for (int r = 0; r < NPH; r++) acc[r] = 0ull;
    const int kbase = kh * 64;
#pragma unroll 2
    for (int kk = 0; kk < 64; kk += 4) {
        const int k = kbase + kk;
        const u64 w0 = *(const u64*)&W[(k+0)*Hd + c0];
        const u64 w1 = *(const u64*)&W[(k+1)*Hd + c0];
        const u64 w2 = *(const u64*)&W[(k+2)*Hd + c0];
        const u64 w3 = *(const u64*)&W[(k+3)*Hd + c0];
#pragma unroll
        for (int r = 0; r < NPH; r++) {
            const ulonglong2 xa = *(const ulonglong2*)&in[r*256 + 2*k];
            const ulonglong2 xb = *(const ulonglong2*)&in[r*256 + 2*k + 4];
            ffma2(acc[r], xa.x, w0);
            ffma2(acc[r], xa.y, w1);
            ffma2(acc[r], xb.x, w2);
            ffma2(acc[r], xb.y, w3);
        }
    }
    float* st = s_stage + (sel*64 + pr) * 20;
    if (kh == 1) {
#pragma unroll
        for (int r = 0; r < NPH; r++) *(u64*)&st[r*2] = acc[r];
    }
    __syncthreads();
    if (kh == 0) {
        const u64 bv = *(const u64*)&b[c0];
        float* outp = sel ? s_out1_dup : s_out0_dup;
#pragma unroll
        for (int r = 0; r < NPH; r++) {
            const u64 v = fadd2(fadd2(acc[r], *(const u64*)&st[r*2]), bv);
            const float2 f = unpack2(v);
            *(float4*)&outp[r*256 + 2*c0] = make_float4(f.x, f.x, f.y, f.y);
        }
    }
    __syncthreads();
}

extern "C" __global__ void __launch_bounds__(TPB, 2)
yomi_kernel(
    const float* __restrict__ x_my,  const float* __restrict__ x_opp,
    const float* __restrict__ W_enc, const float* __restrict__ b_enc,
    const float* __restrict__ gb_Wl, const float* __restrict__ gb_Wr,
    const float* __restrict__ gb_att,const float* __restrict__ gb_b,
    const float* __restrict__ gr_Wl, const float* __restrict__ gr_Wr,
    const float* __restrict__ gr_att,const float* __restrict__ gr_b,
    const float* __restrict__ cl_Wf, const float* __restrict__ cl_bf,
    const float* __restrict__ cl_Ws, const float* __restrict__ cl_bs,
    const float* __restrict__ cr_Wf, const float* __restrict__ cr_bf,
    const float* __restrict__ cr_Ws, const float* __restrict__ cr_bs,
    const float* __restrict__ node_W,const float* __restrict__ node_b,
    const float* __restrict__ W1,    const float* __restrict__ b1,
    const float* __restrict__ W2,    const float* __restrict__ b2,
    float* __restrict__ out)
{
    extern __shared__ float sm[];
    float* s_xm  = sm + OFF_XM;     // dup
    float* s_xo  = sm + OFF_XO;     // dup
    float* s_nm  = sm + OFF_NM;     // dup
    float* s_no  = sm + OFF_NO;     // dup
    float* s_A   = sm + OFF_A;
    float* s_B   = sm + OFF_B;
    float* s_log = sm + OFF_LOG;
    float* s_pool= sm + OFF_POOL;
    float* s_h   = sm + OFF_H;

    const int g = blockIdx.x;
    const int t = threadIdx.x;

    // ---- encoder ----
    {
        for (int idx = t; idx < NPH*CDm; idx += TPB) {
            s_A[idx]           = x_my [g*NPH*CDm + idx];
            s_A[NPH*CDm + idx] = x_opp[g*NPH*CDm + idx];
        }
        __syncthreads();
        const int c = t & 127, sel = t >> 7;
        const float* xg = s_A + sel*NPH*CDm;
        float acc[NPH];
#pragma unroll
        for (int r = 0; r < NPH; r++) acc[r] = 0.f;
#pragma unroll 4
        for (int k = 0; k < CDm; k++) {
            const float w = W_enc[k*Hd + c];
#pragma unroll
            for (int r = 0; r < NPH; r++) acc[r] = fmaf(xg[r*CDm + k], w, acc[r]);
        }
        const float bv = b_enc[c];
        float* dst = sel ? s_xo : s_xm;
#pragma unroll
        for (int r = 0; r < NPH; r++) {
            const float v = acc[r] + bv;
            *(float2*)&dst[r*256 + 2*c] = make_float2(v, v);
        }
        __syncthreads();
    }

    // ---- 2 hetero layers ----
#pragma unroll 1
    for (int l = 0; l < 2; l++) {
        const int wG = l * Hd * 512;
        const int wC = l * 2*Hd * Hd;
        const int wN = l * Hd * Hd;
        const int wb = l * Hd;
        // new_xo = gat_beats(xm->xo) + cg_loses(xm->xo)
        gatv2_block(s_xm, s_xo, gb_Wl + wG, gb_Wr + wG, gb_att + l*4*Hd,
                    gb_b + wb, s_A, s_B, s_log, s_no, false);
        cgconv_block(s_xm, s_xo, cl_Wf + wC, cl_bf + wb, cl_Ws + wC, cl_bs + wb,
                     s_A, s_no, true);
        // new_xm = cg_rev(xo->xm) + gat_rev(xo->xm)
        cgconv_block(s_xo, s_xm, cr_Wf + wC, cr_bf + wb, cr_Ws + wC, cr_bs + wb,
                     s_A, s_nm, false);
        gatv2_block(s_xo, s_xm, gr_Wl + wG, gr_Wr + wG, gr_att + l*4*Hd,
                    gr_b + wb, s_A, s_B, s_log, s_nm, true);
        // node linear
        dual_linear_block(s_nm, s_no, node_W + wN, node_b + wb, s_xm, s_xo, s_A);
    }

    // ---- pool + MLP head ----
    {
        const int c = t & 127, sel = t >> 7;
        const float* xp = sel ? s_xo : s_xm;
        float p = 0.f;
#pragma unroll
        for (int r = 0; r < NPH; r++) p += xp[r*256 + 2*c];
        s_pool[sel*Hd + c] = p * 0.1f;
    }
    __syncthreads();
    {
        const int c = t & 127, half = t >> 7;
        float a = 0.f;
#pragma unroll 4
        for (int kk = 0; kk < Hd; kk++) {
            const int k = half*Hd + kk;
            a = fmaf(s_pool[k], W1[k*Hd + c], a);
        }
        s_h[t] = a;
    }
    __syncthreads();
    if (t < Hd) {
        float hv = s_h[t] + s_h[Hd + t] + b1[t];
        hv = (hv >= 0.f) ? hv : 128.f * hv;   // LeakyReLU slope = final_dim
        s_h[t] = hv * W2[t];
    }
    __syncthreads();
    if (t < 32) {
        float v = s_h[t] + s_h[t+32] + s_h[t+64] + s_h[t+96];
#pragma unroll
        for (int o = 16; o > 0; o >>= 1) v += __shfl_xor_sync(0xffffffffu, v, o);
        if (t == 0) out[g] = v + b2[0];
    }
}

extern "C" void kernel_launch(void* const* d_in, const int* in_sizes, int n_in,
                              void* d_out, int out_size)
{
    const float* x_my   = (const float*)d_in[0];
    const float* x_opp  = (const float*)d_in[1];
    const float* W_enc  = (const float*)d_in[2];
    const float* b_enc  = (const float*)d_in[3];
    const float* gb_Wl  = (const float*)d_in[4];
    const float* gb_Wr  = (const float*)d_in[5];
    const float* gb_att = (const float*)d_in[6];
    const float* gb_b   = (const float*)d_in[7];
    const float* gr_Wl  = (const float*)d_in[8];
    const float* gr_Wr  = (const float*)d_in[9];
    const float* gr_att = (const float*)d_in[10];
    const float* gr_b   = (const float*)d_in[11];
    const float* cl_Wf  = (const float*)d_in[12];
    const float* cl_bf  = (const float*)d_in[13];
    const float* cl_Ws  = (const float*)d_in[14];
    const float* cl_bs  = (const float*)d_in[15];
    const float* cr_Wf  = (const float*)d_in[16];
    const float* cr_bf  = (const float*)d_in[17];
    const float* cr_Ws  = (const float*)d_in[18];
    const float* cr_bs  = (const float*)d_in[19];
    const float* node_W = (const float*)d_in[20];
    const float* node_b = (const float*)d_in[21];
    const float* W1     = (const float*)d_in[22];
    const float* b1     = (const float*)d_in[23];
    const float* W2     = (const float*)d_in[24];
    const float* b2     = (const float*)d_in[25];

    const int n_nodes = in_sizes[0] / CDm;
    const int nblocks = n_nodes / NPH;

    cudaFuncSetAttribute(yomi_kernel,
                         cudaFuncAttributeMaxDynamicSharedMemorySize, SMEM_BYTES);

    yomi_kernel<<<nblocks, TPB, SMEM_BYTES>>>(
        x_my, x_opp, W_enc, b_enc,
        gb_Wl, gb_Wr, gb_att, gb_b,
        gr_Wl, gr_Wr, gr_att, gr_b,
        cl_Wf, cl_bf, cl_Ws, cl_bs,
        cr_Wf, cr_bf, cr_Ws, cr_bs,
        node_W, node_b, W1, b1, W2, b2,
        (float*)d_out);
}